// round 15
// baseline (speedup 1.0000x reference)
#include <cuda_runtime.h>
#include <cuda_fp16.h>
#include <math.h>
#include <stdint.h>

#define Bn 16
#define Qn 300
#define Dn 256
#define Hn 8
#define Pn 4
#define Fn 2048
#define HGn 100
#define WGn 100
#define HWn 10000
#define DHn 32
#define LN_EPS 1e-5f

#define BQ (Bn*Qn)            // 4800
#define MEMROWS (Bn*HWn)      // 160000

typedef unsigned long long ull;

// ---------------- scratch (allocation-free: __device__ globals) ----------------
__device__ float  g_qkv[BQ*3*Dn];
__device__ __half g_sah[BQ*Dn];
__device__ float  g_x1[BQ*Dn];
__device__ float  g_x2[BQ*Dn];
__device__ __half g_x2h[BQ*Dn];
__device__ float  g_tmp[BQ*Dn];
__device__ __half g_cah[BQ*Dn];
__device__ __half g_meh[Hn*BQ*Dn];
__device__ __half g_ffh[BQ*Fn];
__device__ float  g_wcat[Dn*128];
__device__ float  g_bcat[128];
__device__ float  g_lg[BQ*128];
__device__ __half g_tgth[BQ*Dn];
// fp16 k-pair-packed weights
__device__ uint32_t g_pip[(Dn/2)*768];  // in_proj
__device__ uint32_t g_pop[(Dn/2)*Dn];   // out_proj
__device__ uint32_t g_poq[(Dn/2)*Dn];   // oproj
__device__ uint32_t g_pvp[(Dn/2)*Dn];   // vproj
__device__ uint32_t g_p1w[(Dn/2)*Fn];   // lin1
__device__ uint32_t g_p2w[(Fn/2)*Dn];   // lin2

__device__ __forceinline__ ull fma2(ull a, ull b, ull c) {
    ull d;
    asm("fma.rn.f32x2 %0, %1, %2, %3;" : "=l"(d) : "l"(a), "l"(b), "l"(c));
    return d;
}

union F4U { float4 f; ull u[2]; };
union F2U { float2 f; ull u; };

// ---------------- pack all weights into fp16 k-pair half2 ----------------
// dest u32 blocks of 256: ip 384 | op 128 | oq 128 | vp 128 | p1 1024 | p2 1024
__global__ void packw_kernel(
    const float* __restrict__ ipw, const float* __restrict__ opw,
    const float* __restrict__ oqw, const float* __restrict__ vpw,
    const float* __restrict__ l1w, const float* __restrict__ l2w,
    uint32_t* __restrict__ pip, uint32_t* __restrict__ pop,
    uint32_t* __restrict__ poq, uint32_t* __restrict__ pvp,
    uint32_t* __restrict__ p1,  uint32_t* __restrict__ p2)
{
    int bi = blockIdx.x;
    const float* s; uint32_t* d; int N; int base;
    if      (bi <  384) { s = ipw; d = pip; N = 768;  base = bi; }
    else if (bi <  512) { s = opw; d = pop; N = Dn;   base = bi - 384; }
    else if (bi <  640) { s = oqw; d = poq; N = Dn;   base = bi - 512; }
    else if (bi <  768) { s = vpw; d = pvp; N = Dn;   base = bi - 640; }
    else if (bi < 1792) { s = l1w; d = p1;  N = Fn;   base = bi - 768; }
    else                { s = l2w; d = p2;  N = Dn;   base = bi - 1792; }
    int i = base * 256 + threadIdx.x;
    int k2 = i / N, n = i - k2 * N;
    __half2 h = __floats2half2_rn(s[(size_t)(2*k2) * N + n], s[(size_t)(2*k2+1) * N + n]);
    d[i] = *(uint32_t*)&h;
}

// ---------------- convert tgt to half ----------------
__global__ void tgth_kernel(const float4* __restrict__ src, __half2* __restrict__ dst)
{
    int i = blockIdx.x * 256 + threadIdx.x;   // over BQ*Dn/4
    float4 v = src[i];
    dst[2*i]   = __floats2half2_rn(v.x, v.y);
    dst[2*i+1] = __floats2half2_rn(v.z, v.w);
}

// ---------------- common constants ----------------
#define TBN 128
#define BPITCH (TBN + 8)    // 136
#define HBK 32
#define HAP 20

__device__ __forceinline__ void cp16(void* dst, const void* src) {
    uint32_t d = (uint32_t)__cvta_generic_to_shared(dst);
    asm volatile("cp.async.ca.shared.global [%0], [%1], 16;" :: "r"(d), "l"(src));
}

#define MMA_F16(c, a, b) \
    asm volatile( \
        "mma.sync.aligned.m16n8k16.row.col.f32.f16.f16.f32 " \
        "{%0,%1,%2,%3}, {%4,%5,%6,%7}, {%8,%9}, {%0,%1,%2,%3};" \
        : "+f"((c)[0]), "+f"((c)[1]), "+f"((c)[2]), "+f"((c)[3]) \
        : "r"((a)[0]), "r"((a)[1]), "r"((a)[2]), "r"((a)[3]), \
          "r"((b)[0]), "r"((b)[1]))

// ---------------- fp16 64x128 GEMM (m16n8k16), 3-stage cp.async --------------------
__global__ __launch_bounds__(256) void gemm_fp16_async(
    const __half* __restrict__ A, const uint32_t* __restrict__ Wpk,
    const float* __restrict__ bias, void* __restrict__ Cout,
    int M, int N, int K, int relu, int outhalf)
{
    extern __shared__ uint32_t smemu[];
    uint32_t (*As)[64][HAP]    = (uint32_t(*)[64][HAP])smemu;
    uint32_t (*Bs)[16][BPITCH] = (uint32_t(*)[16][BPITCH])(smemu + 3 * 64 * HAP);

    const int tid  = threadIdx.x;
    const int lane = tid & 31;
    const int warp = tid >> 5;
    const int wm = (warp >> 2) * 32;
    const int wn = (warp & 3) * 32;
    const int bm = blockIdx.y * 64;
    const int bn = blockIdx.x * TBN;

    const int lq = lane >> 2;
    const int lr = lane & 3;

    const int a_row = tid >> 2;
    const int a_u32 = (tid & 3) * 4;
    const int b_row = tid >> 4;
    const int b_u32 = (tid & 15) * 8;

    const __half* Aptr = A + (size_t)(bm + a_row) * K + a_u32 * 2;
    const uint32_t* Wptr = Wpk + (size_t)b_row * N + bn + b_u32;

    float c[2][4][4];
#pragma unroll
    for (int i = 0; i < 2; i++)
#pragma unroll
        for (int j = 0; j < 4; j++)
#pragma unroll
            for (int l = 0; l < 4; l++) c[i][j][l] = 0.f;

    const int nk = K / HBK;

#pragma unroll
    for (int s = 0; s < 2; s++) {
        int kt = s * HBK;
        cp16(&As[s][a_row][a_u32], Aptr + kt);
        cp16(&Bs[s][b_row][b_u32],     Wptr + (size_t)(kt / 2) * N);
        cp16(&Bs[s][b_row][b_u32 + 4], Wptr + (size_t)(kt / 2) * N + 4);
        asm volatile("cp.async.commit_group;" ::: "memory");
    }

    for (int it = 0; it < nk; it++) {
        asm volatile("cp.async.wait_group 1;" ::: "memory");
        __syncthreads();

        int nxt = it + 2;
        if (nxt < nk) {
            int s = nxt % 3;
            int kt = nxt * HBK;
            cp16(&As[s][a_row][a_u32], Aptr + kt);
            cp16(&Bs[s][b_row][b_u32],     Wptr + (size_t)(kt / 2) * N);
            cp16(&Bs[s][b_row][b_u32 + 4], Wptr + (size_t)(kt / 2) * N + 4);
        }
        asm volatile("cp.async.commit_group;" ::: "memory");

        const int buf = it % 3;
#pragma unroll
        for (int ks2 = 0; ks2 < 16; ks2 += 8) {
            uint32_t a[2][4], b[4][2];
#pragma unroll
            for (int mt = 0; mt < 2; mt++) {
                int mr = wm + mt * 16 + lq;
                a[mt][0] = As[buf][mr    ][ks2 + lr];
                a[mt][1] = As[buf][mr + 8][ks2 + lr];
                a[mt][2] = As[buf][mr    ][ks2 + lr + 4];
                a[mt][3] = As[buf][mr + 8][ks2 + lr + 4];
            }
#pragma unroll
            for (int nt = 0; nt < 4; nt++) {
                int nc = wn + nt * 8 + lq;
                b[nt][0] = Bs[buf][ks2 + lr    ][nc];
                b[nt][1] = Bs[buf][ks2 + lr + 4][nc];
            }
#pragma unroll
            for (int mt = 0; mt < 2; mt++)
#pragma unroll
                for (int nt = 0; nt < 4; nt++)
                    MMA_F16(c[mt][nt], a[mt], b[nt]);
        }
    }

#pragma unroll
    for (int mt = 0; mt < 2; mt++) {
#pragma unroll
        for (int nt = 0; nt < 4; nt++) {
            int row = bm + wm + mt * 16 + lq;
            int col = bn + wn + nt * 8 + lr * 2;
            float b0 = bias[col], b1 = bias[col + 1];
            float v0 = c[mt][nt][0] + b0;
            float v1 = c[mt][nt][1] + b1;
            float v2 = c[mt][nt][2] + b0;
            float v3 = c[mt][nt][3] + b1;
            if (relu) {
                v0 = fmaxf(v0, 0.f); v1 = fmaxf(v1, 0.f);
                v2 = fmaxf(v2, 0.f); v3 = fmaxf(v3, 0.f);
            }
            if (outhalf) {
                __half* C = (__half*)Cout;
                *(__half2*)&C[(size_t)row * N + col]       = __floats2half2_rn(v0, v1);
                *(__half2*)&C[(size_t)(row + 8) * N + col] = __floats2half2_rn(v2, v3);
            } else {
                float* C = (float*)Cout;
                *(float2*)&C[(size_t)row * N + col]       = make_float2(v0, v1);
                *(float2*)&C[(size_t)(row + 8) * N + col] = make_float2(v2, v3);
            }
        }
    }
}

// ---------------- fp16 per-head projection: [4800,256]@[256,32] x 8 heads ----------
__global__ __launch_bounds__(128) void gemm_proj_h(
    const __half* __restrict__ A, const uint32_t* __restrict__ Wpk,
    const float* __restrict__ bias, __half* __restrict__ C)
{
    __shared__ uint32_t As[3][64][HAP];
    __shared__ uint32_t Bs[3][16][36];

    const int h  = blockIdx.x;       // 0..7
    const int bm = blockIdx.y * 64;
    const int t  = threadIdx.x;      // 0..127
    const int lane = t & 31;
    const int warp = t >> 5;
    const int wm = warp * 16;
    const int lq = lane >> 2;
    const int lr = lane & 3;

    const int a_row = t >> 1;          // 0..63
    const int a_u32 = (t & 1) * 8;     // 0 or 8
    const int b_row = t >> 3;          // 0..15
    const int b_col = (t & 7) * 4;     // 0..28

    const __half* Aptr = A + ((size_t)h * BQ + bm + a_row) * Dn + a_u32 * 2;
    const uint32_t* Wptr = Wpk + (size_t)b_row * Dn + h * 32 + b_col;

    float c[4][4];
#pragma unroll
    for (int j = 0; j < 4; j++)
#pragma unroll
        for (int l = 0; l < 4; l++) c[j][l] = 0.f;

    const int nk = Dn / HBK;  // 8

#pragma unroll
    for (int s = 0; s < 2; s++) {
        int kt = s * HBK;
        cp16(&As[s][a_row][a_u32],     Aptr + kt);
        cp16(&As[s][a_row][a_u32 + 4], Aptr + kt + 8);
        cp16(&Bs[s][b_row][b_col],     Wptr + (size_t)(kt / 2) * Dn);
        asm volatile("cp.async.commit_group;" ::: "memory");
    }

    for (int it = 0; it < nk; it++) {
        asm volatile("cp.async.wait_group 1;" ::: "memory");
        __syncthreads();

        int nxt = it + 2;
        if (nxt < nk) {
            int s = nxt % 3;
            int kt = nxt * HBK;
            cp16(&As[s][a_row][a_u32],     Aptr + kt);
            cp16(&As[s][a_row][a_u32 + 4], Aptr + kt + 8);
            cp16(&Bs[s][b_row][b_col],     Wptr + (size_t)(kt / 2) * Dn);
        }
        asm volatile("cp.async.commit_group;" ::: "memory");

        const int buf = it % 3;
#pragma unroll
        for (int ks2 = 0; ks2 < 16; ks2 += 8) {
            uint32_t a[4], b[4][2];
            int mr = wm + lq;
            a[0] = As[buf][mr    ][ks2 + lr];
            a[1] = As[buf][mr + 8][ks2 + lr];
            a[2] = As[buf][mr    ][ks2 + lr + 4];
            a[3] = As[buf][mr + 8][ks2 + lr + 4];
#pragma unroll
            for (int nt = 0; nt < 4; nt++) {
                int nc = nt * 8 + lq;
                b[nt][0] = Bs[buf][ks2 + lr    ][nc];
                b[nt][1] = Bs[buf][ks2 + lr + 4][nc];
            }
#pragma unroll
            for (int nt = 0; nt < 4; nt++)
                MMA_F16(c[nt], a, b[nt]);
        }
    }

#pragma unroll
    for (int nt = 0; nt < 4; nt++) {
        int row = bm + wm + lq;
        int col = h * 32 + nt * 8 + lr * 2;
        float b0 = bias[col], b1 = bias[col + 1];
        *(__half2*)&C[(size_t)row * Dn + col]       = __floats2half2_rn(c[nt][0] + b0, c[nt][1] + b1);
        *(__half2*)&C[(size_t)(row + 8) * Dn + col] = __floats2half2_rn(c[nt][2] + b0, c[nt][3] + b1);
    }
}

// ---------------- fp32 FFMA tiled SGEMM (accuracy-critical logits) ----------------
#define BM 64
#define BNf 64
#define BKf 16

__global__ __launch_bounds__(256) void gemm_f32_kernel(
    const float* __restrict__ A, const float* __restrict__ W,
    const float* __restrict__ bias, float* __restrict__ C,
    int M, int N, int K)
{
    __shared__ float As[BKf][BM];
    __shared__ float Bs[BKf][BNf];
    int tid = threadIdx.x;
    int tx = tid & 15, ty = tid >> 4;
    int bm = blockIdx.y * BM, bn = blockIdx.x * BNf;

    float acc[4][4];
#pragma unroll
    for (int i = 0; i < 4; i++)
#pragma unroll
        for (int j = 0; j < 4; j++) acc[i][j] = 0.f;

    int a_row = tid >> 2;
    int a_col = (tid & 3) * 4;
    int b_row = tid >> 4;
    int b_col = (tid & 15) * 4;

    const float* Aptr = A + (size_t)(bm + a_row) * K + a_col;
    const float* Wptr = W + (size_t)b_row * N + bn + b_col;

    for (int kt = 0; kt < K; kt += BKf) {
        float4 av = *(const float4*)(Aptr + kt);
        As[a_col + 0][a_row] = av.x;
        As[a_col + 1][a_row] = av.y;
        As[a_col + 2][a_row] = av.z;
        As[a_col + 3][a_row] = av.w;
        float4 bv = *(const float4*)(Wptr + (size_t)kt * N);
        *(float4*)&Bs[b_row][b_col] = bv;
        __syncthreads();
#pragma unroll
        for (int kk = 0; kk < BKf; kk++) {
            float ar[4], br[4];
#pragma unroll
            for (int i = 0; i < 4; i++) ar[i] = As[kk][ty + 16 * i];
#pragma unroll
            for (int j = 0; j < 4; j++) br[j] = Bs[kk][tx + 16 * j];
#pragma unroll
            for (int i = 0; i < 4; i++)
#pragma unroll
                for (int j = 0; j < 4; j++) acc[i][j] += ar[i] * br[j];
        }
        __syncthreads();
    }

#pragma unroll
    for (int i = 0; i < 4; i++) {
        int row = bm + ty + 16 * i;
#pragma unroll
        for (int j = 0; j < 4; j++) {
            int col = bn + tx + 16 * j;
            C[(size_t)row * N + col] = acc[i][j] + bias[col];
        }
    }
}

// ---------------- concat ref/off/attw weights into padded [256,128] ----------------
__global__ void concat_w_kernel(
    const float* __restrict__ ref_w, const float* __restrict__ ref_b,
    const float* __restrict__ off_w, const float* __restrict__ off_b,
    const float* __restrict__ attw_w, const float* __restrict__ attw_b,
    float* __restrict__ Wc, float* __restrict__ bc)
{
    int i = blockIdx.x * 256 + threadIdx.x;
    if (i < Dn * 128) {
        int d = i >> 7, j = i & 127;
        float v = 0.f;
        if (j < 2) v = ref_w[d * 2 + j];
        else if (j < 66) v = off_w[d * 64 + (j - 2)];
        else if (j < 98) v = attw_w[d * 32 + (j - 66)];
        Wc[i] = v;
    }
    if (i < 128) {
        float v = 0.f;
        if (i < 2) v = ref_b[i];
        else if (i < 66) v = off_b[i - 2];
        else if (i < 98) v = attw_b[i - 66];
        bc[i] = v;
    }
}

// ---------------- flash: query-split x2, 2 queries/thread, half output -------------
// grid (2 qsplits, 128 bh), block 96 threads (75 active).
// Thread t (<75) handles queries qs*150+t and qs*150+t+75 over ALL 300 keys;
// normalization stays local (no combine). Numerics identical to prior flash.
#define KT 60

__global__ __launch_bounds__(96) void flash_kernel(
    const float* __restrict__ qkv, __half* __restrict__ sa)
{
    __shared__ float4 Ks[KT][8];
    __shared__ float4 Vs[KT][8];

    const int qs = blockIdx.x;       // 0..1
    const int bh = blockIdx.y;       // 0..127
    const int b = bh >> 3, h = bh & 7;
    const int tid = threadIdx.x;     // 0..95
    const bool act = tid < 75;
    const int qi0 = qs * 150 + (act ? tid : 0);
    const int qi1 = qi0 + (act ? 75 : 0);

    ull q0[16], q1[16], a0[16], a1[16];
    const float* qp0 = qkv + (size_t)(b * Qn + qi0) * (3 * Dn) + h * DHn;
    const float* qp1 = qkv + (size_t)(b * Qn + qi1) * (3 * Dn) + h * DHn;
#pragma unroll
    for (int i = 0; i < 8; i++) {
        F4U t0; t0.f = *(const float4*)(qp0 + i * 4);
        q0[2 * i] = t0.u[0]; q0[2 * i + 1] = t0.u[1];
        F4U t1; t1.f = *(const float4*)(qp1 + i * 4);
        q1[2 * i] = t1.u[0]; q1[2 * i + 1] = t1.u[1];
    }
#pragma unroll
    for (int i = 0; i < 16; i++) { a0[i] = 0ull; a1[i] = 0ull; }

    float su0 = 0.f, su1 = 0.f;
    const float scale = 0.17677669529663689f;

    const float* kbase = qkv + (size_t)(b * Qn) * (3 * Dn) + Dn + h * DHn;
    const float* vbase = kbase + Dn;

    for (int t0 = 0; t0 < Qn; t0 += KT) {
        // cooperative tile load: 480 float4 per array, 96 threads -> 5 each
        for (int i = tid; i < KT * 8; i += 96) {
            int j = i >> 3, dc = i & 7;
            size_t off = (size_t)(t0 + j) * (3 * Dn) + dc * 4;
            Ks[j][dc] = *(const float4*)(kbase + off);
            Vs[j][dc] = *(const float4*)(vbase + off);
        }
        __syncthreads();

#pragma unroll 2
        for (int j = 0; j < KT; j++) {
            F4U w0; w0.f = Ks[j][0]; F4U w1; w1.f = Ks[j][1];
            F4U w2; w2.f = Ks[j][2]; F4U w3; w3.f = Ks[j][3];
            F4U w4; w4.f = Ks[j][4]; F4U w5; w5.f = Ks[j][5];
            F4U w6; w6.f = Ks[j][6]; F4U w7; w7.f = Ks[j][7];
            ull k2a[8] = { w0.u[0], w0.u[1], w1.u[0], w1.u[1],
                           w2.u[0], w2.u[1], w3.u[0], w3.u[1] };
            ull k2b[8] = { w4.u[0], w4.u[1], w5.u[0], w5.u[1],
                           w6.u[0], w6.u[1], w7.u[0], w7.u[1] };

            ull s0a = 0ull, s0b = 0ull, s1a = 0ull, s1b = 0ull;
#pragma unroll
            for (int i = 0; i < 8; i++) {
                s0a = fma2(q0[i], k2a[i], s0a);
                s1a = fma2(q1[i], k2a[i], s1a);
                s0b = fma2(q0[8 + i], k2b[i], s0b);
                s1b = fma2(q1[8 + i], k2b[i], s1b);
            }
            F2U u0a; u0a.u = s0a; F2U u0b; u0b.u = s0b;
            F2U u1a; u1a.u = s1a; F2U u1b; u1b.u = s1b;
            float s0 = (u0a.f.x + u0a.f.y + u0b.f.x + u0b.f.y) * scale;
            float s1 = (u1a.f.x + u1a.f.y + u1b.f.x + u1b.f.y) * scale;
            float p0 = __expf(s0);
            float p1 = __expf(s1);
            su0 += p0;
            su1 += p1;
            F2U pp0; pp0.f = make_float2(p0, p0);
            F2U pp1; pp1.f = make_float2(p1, p1);
            ull p02 = pp0.u, p12 = pp1.u;

            F4U v0; v0.f = Vs[j][0]; F4U v1; v1.f = Vs[j][1];
            F4U v2; v2.f = Vs[j][2]; F4U v3; v3.f = Vs[j][3];
            F4U v4; v4.f = Vs[j][4]; F4U v5; v5.f = Vs[j][5];
            F4U v6; v6.f = Vs[j][6]; F4U v7; v7.f = Vs[j][7];
            ull vv[16] = { v0.u[0], v0.u[1], v1.u[0], v1.u[1],
                           v2.u[0], v2.u[1], v3.u[0], v3.u[1],
                           v4.u[0], v4.u[1], v5.u[0], v5.u[1],
                           v6.u[0], v6.u[1], v7.u[0], v7.u[1] };
#pragma unroll
            for (int i = 0; i < 16; i++) {
                a0[i] = fma2(p02, vv[i], a0[i]);
                a1[i] = fma2(p12, vv[i], a1[i]);
            }
        }
        __syncthreads();
    }

    if (act) {
        float inv0 = 1.f / su0;
        __half* op0 = sa + (size_t)(b * Qn + qi0) * Dn + h * DHn;
#pragma unroll
        for (int i = 0; i < 8; i++) {
            F2U lo; lo.u = a0[2 * i];
            F2U hi; hi.u = a0[2 * i + 1];
            *(__half2*)(op0 + i * 4)     = __floats2half2_rn(lo.f.x * inv0, lo.f.y * inv0);
            *(__half2*)(op0 + i * 4 + 2) = __floats2half2_rn(hi.f.x * inv0, hi.f.y * inv0);
        }
        float inv1 = 1.f / su1;
        __half* op1 = sa + (size_t)(b * Qn + qi1) * Dn + h * DHn;
#pragma unroll
        for (int i = 0; i < 8; i++) {
            F2U lo; lo.u = a1[2 * i];
            F2U hi; hi.u = a1[2 * i + 1];
            *(__half2*)(op1 + i * 4)     = __floats2half2_rn(lo.f.x * inv1, lo.f.y * inv1);
            *(__half2*)(op1 + i * 4 + 2) = __floats2half2_rn(hi.f.x * inv1, hi.f.y * inv1);
        }
    }
}

// ---------------- fused residual-add + LayerNorm (optional half 2nd out) ----------
__global__ void add_ln_kernel(const float* __restrict__ a, const float* __restrict__ r,
                              const float* __restrict__ g, const float* __restrict__ be,
                              float* __restrict__ out, __half* __restrict__ out_h)
{
    int row = blockIdx.x, t = threadIdx.x;
    size_t idx = (size_t)row * Dn + t;
    float v = a[idx] + r[idx];
    __shared__ float red[8];
    float s = v;
#pragma unroll
    for (int o = 16; o; o >>= 1) s += __shfl_xor_sync(~0u, s, o);
    if ((t & 31) == 0) red[t >> 5] = s;
    __syncthreads();
    float mean = 0.f;
#pragma unroll
    for (int i = 0; i < 8; i++) mean += red[i];
    mean *= (1.f / Dn);
    float d = v - mean;
    float s2 = d * d;
#pragma unroll
    for (int o = 16; o; o >>= 1) s2 += __shfl_xor_sync(~0u, s2, o);
    __syncthreads();
    if ((t & 31) == 0) red[t >> 5] = s2;
    __syncthreads();
    float var = 0.f;
#pragma unroll
    for (int i = 0; i < 8; i++) var += red[i];
    var *= (1.f / Dn);
    float o2 = d * rsqrtf(var + LN_EPS) * g[t] + be[t];
    out[idx] = o2;
    if (out_h) out_h[idx] = __float2half(o2);
}

// ---------------- sampler2: weights + bilinear gather of RAW memory -> m_eff (half)
__global__ __launch_bounds__(256) void sampler2_kernel(
    const float* __restrict__ lgbuf, const float* __restrict__ memory,
    __half* __restrict__ me)
{
    __shared__ float lg[128];
    __shared__ float sref[2];
    __shared__ float swts[Hn * Pn];
    __shared__ int   srow[128];
    __shared__ float swt[128];

    int bq = blockIdx.x;
    int b = bq / Qn;
    int t = threadIdx.x;

    if (t < 128) lg[t] = lgbuf[(size_t)bq * 128 + t];
    __syncthreads();

    if (t < 2) sref[t] = 1.f / (1.f + expf(-lg[t]));
    else if (t >= 32 && t < 40) {
        int h = t - 32;
        const float* al = &lg[66 + h * 4];
        float m = fmaxf(fmaxf(al[0], al[1]), fmaxf(al[2], al[3]));
        float e0 = expf(al[0]-m), e1 = expf(al[1]-m), e2 = expf(al[2]-m), e3 = expf(al[3]-m);
        float inv = 1.f / (e0 + e1 + e2 + e3);
        swts[h*4+0] = e0*inv; swts[h*4+1] = e1*inv; swts[h*4+2] = e2*inv; swts[h*4+3] = e3*inv;
    }
    __syncthreads();

    if (t < 32) {
        int h = t >> 2, p = t & 3;
        float lx = fminf(fmaxf(sref[0] + lg[2 + h * 8 + p * 2 + 0], 0.f), 1.f);
        float ly = fminf(fmaxf(sref[1] + lg[2 + h * 8 + p * 2 + 1], 0.f), 1.f);
        float sx = lx * (float)(WGn - 1);
        float sy = ly * (float)(HGn - 1);
        float x0f = floorf(sx), y0f = floorf(sy);
        int x0 = min(max((int)x0f, 0), WGn - 1);
        int y0 = min(max((int)y0f, 0), HGn - 1);
        int x1i = min(x0 + 1, WGn - 1);
        int y1i = min(y0 + 1, HGn - 1);
        float wx1 = sx - x0f, wx0 = 1.f - wx1;
        float wy1 = sy - y0f, wy0 = 1.f - wy1;
        float wp = swts[t];
        int rowb = b * HWn;
        int base = t * 4;
        srow[base + 0] = rowb + y0  * WGn + x0;  swt[base + 0] = wp * wx0 * wy0;
        srow[base + 1] = rowb + y1i * WGn + x0;  swt[base + 1] = wp * wx0 * wy1;
        srow[base + 2] = rowb + y0  * WGn + x1i; swt[base + 2] = wp * wx1 * wy0;
        srow[base + 3] = rowb + y1i * WGn + x1i; swt[base + 3] = wp * wx1 * wy1;
    }
    __syncthreads();

#pragma unroll
    for (int h = 0; h < Hn; h++) {
        float acc = 0.f;
#pragma unroll
        for (int i = 0; i < 16; i++)
            acc += swt[h * 16 + i] * memory[(size_t)srow[h * 16 + i] * Dn + t];
        me[((size_t)h * BQ + bq) * Dn + t] = __float2half(acc);
    }
}

// ---------------- launch ----------------
extern "C" void kernel_launch(void* const* d_in, const int* in_sizes, int n_in,
                              void* d_out, int out_size)
{
    const float* tgt        = (const float*)d_in[0];
    const float* memory     = (const float*)d_in[1];
    const float* in_proj_w  = (const float*)d_in[2];
    const float* in_proj_b  = (const float*)d_in[3];
    const float* out_proj_w = (const float*)d_in[4];
    const float* out_proj_b = (const float*)d_in[5];
    const float* norm1_g    = (const float*)d_in[6];
    const float* norm1_b    = (const float*)d_in[7];
    const float* ref_w      = (const float*)d_in[8];
    const float* ref_b      = (const float*)d_in[9];
    const float* off_w      = (const float*)d_in[10];
    const float* off_b      = (const float*)d_in[11];
    const float* attw_w     = (const float*)d_in[12];
    const float* attw_b     = (const float*)d_in[13];
    const float* vproj_w    = (const float*)d_in[14];
    const float* vproj_b    = (const float*)d_in[15];
    const float* oproj_w    = (const float*)d_in[16];
    const float* oproj_b    = (const float*)d_in[17];
    const float* norm2_g    = (const float*)d_in[18];
    const float* norm2_b    = (const float*)d_in[19];
    const float* lin1_w     = (const float*)d_in[20];
    const float* lin1_b     = (const float*)d_in[21];
    const float* lin2_w     = (const float*)d_in[22];
    const float* lin2_b     = (const float*)d_in[23];
    const float* norm3_g    = (const float*)d_in[24];
    const float* norm3_b    = (const float*)d_in[25];
    float* out = (float*)d_out;

    float *qkv, *x1, *x2, *tmp, *wcat, *bcat, *lgb;
    __half *sah, *x2h, *cah, *meh, *ffh, *tgth;
    uint32_t *pip, *pop, *poq, *pvp, *p1w, *p2w;
    cudaGetSymbolAddress((void**)&qkv,  g_qkv);
    cudaGetSymbolAddress((void**)&sah,  g_sah);
    cudaGetSymbolAddress((void**)&x1,   g_x1);
    cudaGetSymbolAddress((void**)&x2,   g_x2);
    cudaGetSymbolAddress((void**)&x2h,  g_x2h);
    cudaGetSymbolAddress((void**)&tmp,  g_tmp);
    cudaGetSymbolAddress((void**)&cah,  g_cah);
    cudaGetSymbolAddress((void**)&meh,  g_meh);
    cudaGetSymbolAddress((void**)&ffh,  g_ffh);
    cudaGetSymbolAddress((void**)&wcat, g_wcat);
    cudaGetSymbolAddress((void**)&bcat, g_bcat);
    cudaGetSymbolAddress((void**)&lgb,  g_lg);
    cudaGetSymbolAddress((void**)&tgth, g_tgth);
    cudaGetSymbolAddress((void**)&pip,  g_pip);
    cudaGetSymbolAddress((void**)&pop,  g_pop);
    cudaGetSymbolAddress((void**)&poq,  g_poq);
    cudaGetSymbolAddress((void**)&pvp,  g_pvp);
    cudaGetSymbolAddress((void**)&p1w,  g_p1w);
    cudaGetSymbolAddress((void**)&p2w,  g_p2w);

    const int smemh = (3 * 64 * HAP + 3 * 16 * BPITCH) * 4;  // 41472
    cudaFuncSetAttribute((const void*)gemm_fp16_async, cudaFuncAttributeMaxDynamicSharedMemorySize, smemh);

    // 0. pack all weights fp16; convert tgt to half; concat logits weights (fp32)
    packw_kernel<<<2816, 256>>>(in_proj_w, out_proj_w, oproj_w, vproj_w, lin1_w, lin2_w,
                                pip, pop, poq, pvp, p1w, p2w);
    tgth_kernel<<<BQ * Dn / 1024, 256>>>((const float4*)tgt, (__half2*)tgth);
    concat_w_kernel<<<128, 256>>>(ref_w, ref_b, off_w, off_b, attw_w, attw_b, wcat, bcat);
    // 1. qkv projection [4800,256]@[256,768] — fp16, fp32 out
    gemm_fp16_async<<<dim3(768 / TBN, BQ / 64), 256, smemh>>>(tgth, pip, in_proj_b, qkv, BQ, 768, Dn, 0, 0);
    // 2. fused self-attention: query-split x2, 2q/thread, half out
    flash_kernel<<<dim3(2, Bn * Hn), 96>>>(qkv, sah);
    // 3. out_proj — fp16, fp32 out
    gemm_fp16_async<<<dim3(Dn / TBN, BQ / 64), 256, smemh>>>(sah, pop, out_proj_b, tmp, BQ, Dn, Dn, 0, 0);
    // 4. x1 = LN(tgt + sa_out)
    add_ln_kernel<<<BQ, Dn>>>(tgt, tmp, norm1_g, norm1_b, x1, nullptr);
    // 5. logits — fp32 (accuracy-critical)
    gemm_f32_kernel<<<dim3(128 / BNf, BQ / BM), 256>>>(x1, wcat, bcat, lgb, BQ, 128, Dn);
    // 6. sampler2: gather raw memory -> half m_eff
    sampler2_kernel<<<BQ, 256>>>(lgb, memory, meh);
    // 7. per-head projection — fp16, half out
    gemm_proj_h<<<dim3(Hn, BQ / 64), 128>>>(meh, pvp, vproj_b, cah);
    // 8. oproj — fp16, fp32 out
    gemm_fp16_async<<<dim3(Dn / TBN, BQ / 64), 256, smemh>>>(cah, poq, oproj_b, tmp, BQ, Dn, Dn, 0, 0);
    // 9. x2 = LN(x1 + ca_out); x2h = half(x2)
    add_ln_kernel<<<BQ, Dn>>>(x1, tmp, norm2_g, norm2_b, x2, x2h);
    // 10. FFN lin1 + ReLU — fp16, half out
    gemm_fp16_async<<<dim3(Fn / TBN, BQ / 64), 256, smemh>>>(x2h, p1w, lin1_b, ffh, BQ, Fn, Dn, 1, 1);
    // 11. FFN lin2 — fp16, fp32 out
    gemm_fp16_async<<<dim3(Dn / TBN, BQ / 64), 256, smemh>>>(ffh, p2w, lin2_b, tmp, BQ, Dn, Fn, 0, 0);
    // 12. out = LN(x2 + ffn)
    add_ln_kernel<<<BQ, Dn>>>(x2, tmp, norm3_g, norm3_b, out, nullptr);
}

// round 16
// speedup vs baseline: 1.0164x; 1.0164x over previous
#include <cuda_runtime.h>
#include <cuda_fp16.h>
#include <math.h>
#include <stdint.h>

#define Bn 16
#define Qn 300
#define Dn 256
#define Hn 8
#define Pn 4
#define Fn 2048
#define HGn 100
#define WGn 100
#define HWn 10000
#define DHn 32
#define LN_EPS 1e-5f

#define BQ (Bn*Qn)            // 4800
#define MEMROWS (Bn*HWn)      // 160000

typedef unsigned long long ull;

// ---------------- scratch (allocation-free: __device__ globals) ----------------
__device__ float  g_qkv[BQ*3*Dn];
__device__ __half g_sah[BQ*Dn];
__device__ float  g_x1[BQ*Dn];
__device__ float  g_x2[BQ*Dn];
__device__ __half g_x2h[BQ*Dn];
__device__ float  g_tmp[BQ*Dn];
__device__ __half g_cah[BQ*Dn];
__device__ __half g_meh[Hn*BQ*Dn];
__device__ __half g_ffh[BQ*Fn];
__device__ float  g_wcat[Dn*128];
__device__ float  g_bcat[128];
__device__ float  g_lg[BQ*128];
__device__ __half g_tgth[BQ*Dn];
// fp16 k-pair-packed weights
__device__ uint32_t g_pip[(Dn/2)*768];  // in_proj
__device__ uint32_t g_pop[(Dn/2)*Dn];   // out_proj
__device__ uint32_t g_poq[(Dn/2)*Dn];   // oproj
__device__ uint32_t g_pvp[(Dn/2)*Dn];   // vproj
__device__ uint32_t g_p1w[(Dn/2)*Fn];   // lin1
__device__ uint32_t g_p2w[(Fn/2)*Dn];   // lin2

__device__ __forceinline__ ull fma2(ull a, ull b, ull c) {
    ull d;
    asm("fma.rn.f32x2 %0, %1, %2, %3;" : "=l"(d) : "l"(a), "l"(b), "l"(c));
    return d;
}

union F4U { float4 f; ull u[2]; };
union F2U { float2 f; ull u; };

// ---------------- pack weights + tgt into fp16 (k-pair half2 / consecutive pairs) --
// dest u32 blocks of 256: ip 384 | op 128 | oq 128 | vp 128 | p1 1024 | p2 1024 | tgt 2400
// (tgt uses N=1 => consecutive-element pairing = straight half conversion)
__global__ void packw_kernel(
    const float* __restrict__ ipw, const float* __restrict__ opw,
    const float* __restrict__ oqw, const float* __restrict__ vpw,
    const float* __restrict__ l1w, const float* __restrict__ l2w,
    const float* __restrict__ tgt,
    uint32_t* __restrict__ pip, uint32_t* __restrict__ pop,
    uint32_t* __restrict__ poq, uint32_t* __restrict__ pvp,
    uint32_t* __restrict__ p1,  uint32_t* __restrict__ p2,
    uint32_t* __restrict__ ptg)
{
    int bi = blockIdx.x;
    const float* s; uint32_t* d; int N; int base;
    if      (bi <  384) { s = ipw; d = pip; N = 768;  base = bi; }
    else if (bi <  512) { s = opw; d = pop; N = Dn;   base = bi - 384; }
    else if (bi <  640) { s = oqw; d = poq; N = Dn;   base = bi - 512; }
    else if (bi <  768) { s = vpw; d = pvp; N = Dn;   base = bi - 640; }
    else if (bi < 1792) { s = l1w; d = p1;  N = Fn;   base = bi - 768; }
    else if (bi < 2816) { s = l2w; d = p2;  N = Dn;   base = bi - 1792; }
    else                { s = tgt; d = ptg; N = 1;    base = bi - 2816; }
    int i = base * 256 + threadIdx.x;
    int k2 = i / N, n = i - k2 * N;
    __half2 h = __floats2half2_rn(s[(size_t)(2*k2) * N + n], s[(size_t)(2*k2+1) * N + n]);
    d[i] = *(uint32_t*)&h;
}

// ---------------- common constants ----------------
#define TBN 128
#define BPITCH (TBN + 8)    // 136
#define HBK 32
#define HAP 20

__device__ __forceinline__ void cp16(void* dst, const void* src) {
    uint32_t d = (uint32_t)__cvta_generic_to_shared(dst);
    asm volatile("cp.async.ca.shared.global [%0], [%1], 16;" :: "r"(d), "l"(src));
}

#define MMA_F16(c, a, b) \
    asm volatile( \
        "mma.sync.aligned.m16n8k16.row.col.f32.f16.f16.f32 " \
        "{%0,%1,%2,%3}, {%4,%5,%6,%7}, {%8,%9}, {%0,%1,%2,%3};" \
        : "+f"((c)[0]), "+f"((c)[1]), "+f"((c)[2]), "+f"((c)[3]) \
        : "r"((a)[0]), "r"((a)[1]), "r"((a)[2]), "r"((a)[3]), \
          "r"((b)[0]), "r"((b)[1]))

// ---------------- fp16 64x128 GEMM (m16n8k16), 3-stage cp.async --------------------
__global__ __launch_bounds__(256) void gemm_fp16_async(
    const __half* __restrict__ A, const uint32_t* __restrict__ Wpk,
    const float* __restrict__ bias, void* __restrict__ Cout,
    int M, int N, int K, int relu, int outhalf)
{
    extern __shared__ uint32_t smemu[];
    uint32_t (*As)[64][HAP]    = (uint32_t(*)[64][HAP])smemu;
    uint32_t (*Bs)[16][BPITCH] = (uint32_t(*)[16][BPITCH])(smemu + 3 * 64 * HAP);

    const int tid  = threadIdx.x;
    const int lane = tid & 31;
    const int warp = tid >> 5;
    const int wm = (warp >> 2) * 32;
    const int wn = (warp & 3) * 32;
    const int bm = blockIdx.y * 64;
    const int bn = blockIdx.x * TBN;

    const int lq = lane >> 2;
    const int lr = lane & 3;

    const int a_row = tid >> 2;
    const int a_u32 = (tid & 3) * 4;
    const int b_row = tid >> 4;
    const int b_u32 = (tid & 15) * 8;

    const __half* Aptr = A + (size_t)(bm + a_row) * K + a_u32 * 2;
    const uint32_t* Wptr = Wpk + (size_t)b_row * N + bn + b_u32;

    float c[2][4][4];
#pragma unroll
    for (int i = 0; i < 2; i++)
#pragma unroll
        for (int j = 0; j < 4; j++)
#pragma unroll
            for (int l = 0; l < 4; l++) c[i][j][l] = 0.f;

    const int nk = K / HBK;

#pragma unroll
    for (int s = 0; s < 2; s++) {
        int kt = s * HBK;
        cp16(&As[s][a_row][a_u32], Aptr + kt);
        cp16(&Bs[s][b_row][b_u32],     Wptr + (size_t)(kt / 2) * N);
        cp16(&Bs[s][b_row][b_u32 + 4], Wptr + (size_t)(kt / 2) * N + 4);
        asm volatile("cp.async.commit_group;" ::: "memory");
    }

    for (int it = 0; it < nk; it++) {
        asm volatile("cp.async.wait_group 1;" ::: "memory");
        __syncthreads();

        int nxt = it + 2;
        if (nxt < nk) {
            int s = nxt % 3;
            int kt = nxt * HBK;
            cp16(&As[s][a_row][a_u32], Aptr + kt);
            cp16(&Bs[s][b_row][b_u32],     Wptr + (size_t)(kt / 2) * N);
            cp16(&Bs[s][b_row][b_u32 + 4], Wptr + (size_t)(kt / 2) * N + 4);
        }
        asm volatile("cp.async.commit_group;" ::: "memory");

        const int buf = it % 3;
#pragma unroll
        for (int ks2 = 0; ks2 < 16; ks2 += 8) {
            uint32_t a[2][4], b[4][2];
#pragma unroll
            for (int mt = 0; mt < 2; mt++) {
                int mr = wm + mt * 16 + lq;
                a[mt][0] = As[buf][mr    ][ks2 + lr];
                a[mt][1] = As[buf][mr + 8][ks2 + lr];
                a[mt][2] = As[buf][mr    ][ks2 + lr + 4];
                a[mt][3] = As[buf][mr + 8][ks2 + lr + 4];
            }
#pragma unroll
            for (int nt = 0; nt < 4; nt++) {
                int nc = wn + nt * 8 + lq;
                b[nt][0] = Bs[buf][ks2 + lr    ][nc];
                b[nt][1] = Bs[buf][ks2 + lr + 4][nc];
            }
#pragma unroll
            for (int mt = 0; mt < 2; mt++)
#pragma unroll
                for (int nt = 0; nt < 4; nt++)
                    MMA_F16(c[mt][nt], a[mt], b[nt]);
        }
    }

#pragma unroll
    for (int mt = 0; mt < 2; mt++) {
#pragma unroll
        for (int nt = 0; nt < 4; nt++) {
            int row = bm + wm + mt * 16 + lq;
            int col = bn + wn + nt * 8 + lr * 2;
            float b0 = bias[col], b1 = bias[col + 1];
            float v0 = c[mt][nt][0] + b0;
            float v1 = c[mt][nt][1] + b1;
            float v2 = c[mt][nt][2] + b0;
            float v3 = c[mt][nt][3] + b1;
            if (relu) {
                v0 = fmaxf(v0, 0.f); v1 = fmaxf(v1, 0.f);
                v2 = fmaxf(v2, 0.f); v3 = fmaxf(v3, 0.f);
            }
            if (outhalf) {
                __half* C = (__half*)Cout;
                *(__half2*)&C[(size_t)row * N + col]       = __floats2half2_rn(v0, v1);
                *(__half2*)&C[(size_t)(row + 8) * N + col] = __floats2half2_rn(v2, v3);
            } else {
                float* C = (float*)Cout;
                *(float2*)&C[(size_t)row * N + col]       = make_float2(v0, v1);
                *(float2*)&C[(size_t)(row + 8) * N + col] = make_float2(v2, v3);
            }
        }
    }
}

// ---------------- fp16 per-head projection: [4800,256]@[256,32] x 8 heads ----------
__global__ __launch_bounds__(128) void gemm_proj_h(
    const __half* __restrict__ A, const uint32_t* __restrict__ Wpk,
    const float* __restrict__ bias, __half* __restrict__ C)
{
    __shared__ uint32_t As[3][64][HAP];
    __shared__ uint32_t Bs[3][16][36];

    const int h  = blockIdx.x;       // 0..7
    const int bm = blockIdx.y * 64;
    const int t  = threadIdx.x;      // 0..127
    const int lane = t & 31;
    const int warp = t >> 5;
    const int wm = warp * 16;
    const int lq = lane >> 2;
    const int lr = lane & 3;

    const int a_row = t >> 1;          // 0..63
    const int a_u32 = (t & 1) * 8;     // 0 or 8
    const int b_row = t >> 3;          // 0..15
    const int b_col = (t & 7) * 4;     // 0..28

    const __half* Aptr = A + ((size_t)h * BQ + bm + a_row) * Dn + a_u32 * 2;
    const uint32_t* Wptr = Wpk + (size_t)b_row * Dn + h * 32 + b_col;

    float c[4][4];
#pragma unroll
    for (int j = 0; j < 4; j++)
#pragma unroll
        for (int l = 0; l < 4; l++) c[j][l] = 0.f;

    const int nk = Dn / HBK;  // 8

#pragma unroll
    for (int s = 0; s < 2; s++) {
        int kt = s * HBK;
        cp16(&As[s][a_row][a_u32],     Aptr + kt);
        cp16(&As[s][a_row][a_u32 + 4], Aptr + kt + 8);
        cp16(&Bs[s][b_row][b_col],     Wptr + (size_t)(kt / 2) * Dn);
        asm volatile("cp.async.commit_group;" ::: "memory");
    }

    for (int it = 0; it < nk; it++) {
        asm volatile("cp.async.wait_group 1;" ::: "memory");
        __syncthreads();

        int nxt = it + 2;
        if (nxt < nk) {
            int s = nxt % 3;
            int kt = nxt * HBK;
            cp16(&As[s][a_row][a_u32],     Aptr + kt);
            cp16(&As[s][a_row][a_u32 + 4], Aptr + kt + 8);
            cp16(&Bs[s][b_row][b_col],     Wptr + (size_t)(kt / 2) * Dn);
        }
        asm volatile("cp.async.commit_group;" ::: "memory");

        const int buf = it % 3;
#pragma unroll
        for (int ks2 = 0; ks2 < 16; ks2 += 8) {
            uint32_t a[4], b[4][2];
            int mr = wm + lq;
            a[0] = As[buf][mr    ][ks2 + lr];
            a[1] = As[buf][mr + 8][ks2 + lr];
            a[2] = As[buf][mr    ][ks2 + lr + 4];
            a[3] = As[buf][mr + 8][ks2 + lr + 4];
#pragma unroll
            for (int nt = 0; nt < 4; nt++) {
                int nc = nt * 8 + lq;
                b[nt][0] = Bs[buf][ks2 + lr    ][nc];
                b[nt][1] = Bs[buf][ks2 + lr + 4][nc];
            }
#pragma unroll
            for (int nt = 0; nt < 4; nt++)
                MMA_F16(c[nt], a, b[nt]);
        }
    }

#pragma unroll
    for (int nt = 0; nt < 4; nt++) {
        int row = bm + wm + lq;
        int col = h * 32 + nt * 8 + lr * 2;
        float b0 = bias[col], b1 = bias[col + 1];
        *(__half2*)&C[(size_t)row * Dn + col]       = __floats2half2_rn(c[nt][0] + b0, c[nt][1] + b1);
        *(__half2*)&C[(size_t)(row + 8) * Dn + col] = __floats2half2_rn(c[nt][2] + b0, c[nt][3] + b1);
    }
}

// ---------------- fp32 FFMA tiled SGEMM (accuracy-critical logits) ----------------
#define BM 64
#define BNf 64
#define BKf 16

__global__ __launch_bounds__(256) void gemm_f32_kernel(
    const float* __restrict__ A, const float* __restrict__ W,
    const float* __restrict__ bias, float* __restrict__ C,
    int M, int N, int K)
{
    __shared__ float As[BKf][BM];
    __shared__ float Bs[BKf][BNf];
    int tid = threadIdx.x;
    int tx = tid & 15, ty = tid >> 4;
    int bm = blockIdx.y * BM, bn = blockIdx.x * BNf;

    float acc[4][4];
#pragma unroll
    for (int i = 0; i < 4; i++)
#pragma unroll
        for (int j = 0; j < 4; j++) acc[i][j] = 0.f;

    int a_row = tid >> 2;
    int a_col = (tid & 3) * 4;
    int b_row = tid >> 4;
    int b_col = (tid & 15) * 4;

    const float* Aptr = A + (size_t)(bm + a_row) * K + a_col;
    const float* Wptr = W + (size_t)b_row * N + bn + b_col;

    for (int kt = 0; kt < K; kt += BKf) {
        float4 av = *(const float4*)(Aptr + kt);
        As[a_col + 0][a_row] = av.x;
        As[a_col + 1][a_row] = av.y;
        As[a_col + 2][a_row] = av.z;
        As[a_col + 3][a_row] = av.w;
        float4 bv = *(const float4*)(Wptr + (size_t)kt * N);
        *(float4*)&Bs[b_row][b_col] = bv;
        __syncthreads();
#pragma unroll
        for (int kk = 0; kk < BKf; kk++) {
            float ar[4], br[4];
#pragma unroll
            for (int i = 0; i < 4; i++) ar[i] = As[kk][ty + 16 * i];
#pragma unroll
            for (int j = 0; j < 4; j++) br[j] = Bs[kk][tx + 16 * j];
#pragma unroll
            for (int i = 0; i < 4; i++)
#pragma unroll
                for (int j = 0; j < 4; j++) acc[i][j] += ar[i] * br[j];
        }
        __syncthreads();
    }

#pragma unroll
    for (int i = 0; i < 4; i++) {
        int row = bm + ty + 16 * i;
#pragma unroll
        for (int j = 0; j < 4; j++) {
            int col = bn + tx + 16 * j;
            C[(size_t)row * N + col] = acc[i][j] + bias[col];
        }
    }
}

// ---------------- concat ref/off/attw weights into padded [256,128] ----------------
__global__ void concat_w_kernel(
    const float* __restrict__ ref_w, const float* __restrict__ ref_b,
    const float* __restrict__ off_w, const float* __restrict__ off_b,
    const float* __restrict__ attw_w, const float* __restrict__ attw_b,
    float* __restrict__ Wc, float* __restrict__ bc)
{
    int i = blockIdx.x * 256 + threadIdx.x;
    if (i < Dn * 128) {
        int d = i >> 7, j = i & 127;
        float v = 0.f;
        if (j < 2) v = ref_w[d * 2 + j];
        else if (j < 66) v = off_w[d * 64 + (j - 2)];
        else if (j < 98) v = attw_w[d * 32 + (j - 66)];
        Wc[i] = v;
    }
    if (i < 128) {
        float v = 0.f;
        if (i < 2) v = ref_b[i];
        else if (i < 66) v = off_b[i - 2];
        else if (i < 98) v = attw_b[i - 66];
        bc[i] = v;
    }
}

// ---------------- flash: R14 shape + cp.async double-buffered K/V tiles ------------
// grid 128 (bh), 160 threads; thread t handles queries t, t+160.
#define KT 60

__global__ __launch_bounds__(160) void flash_kernel(
    const float* __restrict__ qkv, __half* __restrict__ sa)
{
    __shared__ float4 Ks[2][KT][8];
    __shared__ float4 Vs[2][KT][8];

    const int bh = blockIdx.x;
    const int b = bh >> 3, h = bh & 7;
    const int tid = threadIdx.x;
    const int qi0 = tid;
    const int qi1 = tid + 160;
    const bool act1 = qi1 < Qn;

    ull q0[16], q1[16], a0[16], a1[16];
    const float* qp0 = qkv + (size_t)(b * Qn + qi0) * (3 * Dn) + h * DHn;
    const float* qp1 = qkv + (size_t)(b * Qn + (act1 ? qi1 : 0)) * (3 * Dn) + h * DHn;
#pragma unroll
    for (int i = 0; i < 8; i++) {
        F4U t0; t0.f = *(const float4*)(qp0 + i * 4);
        q0[2 * i] = t0.u[0]; q0[2 * i + 1] = t0.u[1];
        F4U t1; t1.f = *(const float4*)(qp1 + i * 4);
        q1[2 * i] = t1.u[0]; q1[2 * i + 1] = t1.u[1];
    }
#pragma unroll
    for (int i = 0; i < 16; i++) { a0[i] = 0ull; a1[i] = 0ull; }

    float su0 = 0.f, su1 = 0.f;
    const float scale = 0.17677669529663689f;

    const float* kbase = qkv + (size_t)(b * Qn) * (3 * Dn) + Dn + h * DHn;
    const float* vbase = kbase + Dn;

    const int ntiles = Qn / KT;  // 5

    // prologue: issue tile 0 into buffer 0
    {
        for (int i = tid; i < KT * 8; i += 160) {
            int j = i >> 3, dc = i & 7;
            size_t off = (size_t)j * (3 * Dn) + dc * 4;
            cp16(&Ks[0][j][dc], kbase + off);
            cp16(&Vs[0][j][dc], vbase + off);
        }
        asm volatile("cp.async.commit_group;" ::: "memory");
    }

    for (int it = 0; it < ntiles; it++) {
        asm volatile("cp.async.wait_group 0;" ::: "memory");
        __syncthreads();

        // issue next tile into the other buffer while computing this one
        if (it + 1 < ntiles) {
            int nb = (it + 1) & 1;
            int t0n = (it + 1) * KT;
            for (int i = tid; i < KT * 8; i += 160) {
                int j = i >> 3, dc = i & 7;
                size_t off = (size_t)(t0n + j) * (3 * Dn) + dc * 4;
                cp16(&Ks[nb][j][dc], kbase + off);
                cp16(&Vs[nb][j][dc], vbase + off);
            }
            asm volatile("cp.async.commit_group;" ::: "memory");
        }

        const int buf = it & 1;
#pragma unroll 2
        for (int j = 0; j < KT; j++) {
            F4U w0; w0.f = Ks[buf][j][0]; F4U w1; w1.f = Ks[buf][j][1];
            F4U w2; w2.f = Ks[buf][j][2]; F4U w3; w3.f = Ks[buf][j][3];
            F4U w4; w4.f = Ks[buf][j][4]; F4U w5; w5.f = Ks[buf][j][5];
            F4U w6; w6.f = Ks[buf][j][6]; F4U w7; w7.f = Ks[buf][j][7];
            ull k2a[8] = { w0.u[0], w0.u[1], w1.u[0], w1.u[1],
                           w2.u[0], w2.u[1], w3.u[0], w3.u[1] };
            ull k2b[8] = { w4.u[0], w4.u[1], w5.u[0], w5.u[1],
                           w6.u[0], w6.u[1], w7.u[0], w7.u[1] };

            ull s0a = 0ull, s0b = 0ull, s1a = 0ull, s1b = 0ull;
#pragma unroll
            for (int i = 0; i < 8; i++) {
                s0a = fma2(q0[i], k2a[i], s0a);
                s1a = fma2(q1[i], k2a[i], s1a);
                s0b = fma2(q0[8 + i], k2b[i], s0b);
                s1b = fma2(q1[8 + i], k2b[i], s1b);
            }
            F2U u0a; u0a.u = s0a; F2U u0b; u0b.u = s0b;
            F2U u1a; u1a.u = s1a; F2U u1b; u1b.u = s1b;
            float s0 = (u0a.f.x + u0a.f.y + u0b.f.x + u0b.f.y) * scale;
            float s1 = (u1a.f.x + u1a.f.y + u1b.f.x + u1b.f.y) * scale;
            float p0 = __expf(s0);
            float p1 = __expf(s1);
            su0 += p0;
            su1 += p1;
            F2U pp0; pp0.f = make_float2(p0, p0);
            F2U pp1; pp1.f = make_float2(p1, p1);
            ull p02 = pp0.u, p12 = pp1.u;

            F4U v0; v0.f = Vs[buf][j][0]; F4U v1; v1.f = Vs[buf][j][1];
            F4U v2; v2.f = Vs[buf][j][2]; F4U v3; v3.f = Vs[buf][j][3];
            F4U v4; v4.f = Vs[buf][j][4]; F4U v5; v5.f = Vs[buf][j][5];
            F4U v6; v6.f = Vs[buf][j][6]; F4U v7; v7.f = Vs[buf][j][7];
            ull vv[16] = { v0.u[0], v0.u[1], v1.u[0], v1.u[1],
                           v2.u[0], v2.u[1], v3.u[0], v3.u[1],
                           v4.u[0], v4.u[1], v5.u[0], v5.u[1],
                           v6.u[0], v6.u[1], v7.u[0], v7.u[1] };
#pragma unroll
            for (int i = 0; i < 16; i++) {
                a0[i] = fma2(p02, vv[i], a0[i]);
                a1[i] = fma2(p12, vv[i], a1[i]);
            }
        }
        __syncthreads();
    }

    {
        float inv0 = 1.f / su0;
        __half* op0 = sa + (size_t)(b * Qn + qi0) * Dn + h * DHn;
#pragma unroll
        for (int i = 0; i < 8; i++) {
            F2U lo; lo.u = a0[2 * i];
            F2U hi; hi.u = a0[2 * i + 1];
            *(__half2*)(op0 + i * 4)     = __floats2half2_rn(lo.f.x * inv0, lo.f.y * inv0);
            *(__half2*)(op0 + i * 4 + 2) = __floats2half2_rn(hi.f.x * inv0, hi.f.y * inv0);
        }
    }
    if (act1) {
        float inv1 = 1.f / su1;
        __half* op1 = sa + (size_t)(b * Qn + qi1) * Dn + h * DHn;
#pragma unroll
        for (int i = 0; i < 8; i++) {
            F2U lo; lo.u = a1[2 * i];
            F2U hi; hi.u = a1[2 * i + 1];
            *(__half2*)(op1 + i * 4)     = __floats2half2_rn(lo.f.x * inv1, lo.f.y * inv1);
            *(__half2*)(op1 + i * 4 + 2) = __floats2half2_rn(hi.f.x * inv1, hi.f.y * inv1);
        }
    }
}

// ---------------- fused residual-add + LayerNorm (optional half 2nd out) ----------
__global__ void add_ln_kernel(const float* __restrict__ a, const float* __restrict__ r,
                              const float* __restrict__ g, const float* __restrict__ be,
                              float* __restrict__ out, __half* __restrict__ out_h)
{
    int row = blockIdx.x, t = threadIdx.x;
    size_t idx = (size_t)row * Dn + t;
    float v = a[idx] + r[idx];
    __shared__ float red[8];
    float s = v;
#pragma unroll
    for (int o = 16; o; o >>= 1) s += __shfl_xor_sync(~0u, s, o);
    if ((t & 31) == 0) red[t >> 5] = s;
    __syncthreads();
    float mean = 0.f;
#pragma unroll
    for (int i = 0; i < 8; i++) mean += red[i];
    mean *= (1.f / Dn);
    float d = v - mean;
    float s2 = d * d;
#pragma unroll
    for (int o = 16; o; o >>= 1) s2 += __shfl_xor_sync(~0u, s2, o);
    __syncthreads();
    if ((t & 31) == 0) red[t >> 5] = s2;
    __syncthreads();
    float var = 0.f;
#pragma unroll
    for (int i = 0; i < 8; i++) var += red[i];
    var *= (1.f / Dn);
    float o2 = d * rsqrtf(var + LN_EPS) * g[t] + be[t];
    out[idx] = o2;
    if (out_h) out_h[idx] = __float2half(o2);
}

// ---------------- sampler2: weights + bilinear gather of RAW memory -> m_eff (half)
__global__ __launch_bounds__(256) void sampler2_kernel(
    const float* __restrict__ lgbuf, const float* __restrict__ memory,
    __half* __restrict__ me)
{
    __shared__ float lg[128];
    __shared__ float sref[2];
    __shared__ float swts[Hn * Pn];
    __shared__ int   srow[128];
    __shared__ float swt[128];

    int bq = blockIdx.x;
    int b = bq / Qn;
    int t = threadIdx.x;

    if (t < 128) lg[t] = lgbuf[(size_t)bq * 128 + t];
    __syncthreads();

    if (t < 2) sref[t] = 1.f / (1.f + expf(-lg[t]));
    else if (t >= 32 && t < 40) {
        int h = t - 32;
        const float* al = &lg[66 + h * 4];
        float m = fmaxf(fmaxf(al[0], al[1]), fmaxf(al[2], al[3]));
        float e0 = expf(al[0]-m), e1 = expf(al[1]-m), e2 = expf(al[2]-m), e3 = expf(al[3]-m);
        float inv = 1.f / (e0 + e1 + e2 + e3);
        swts[h*4+0] = e0*inv; swts[h*4+1] = e1*inv; swts[h*4+2] = e2*inv; swts[h*4+3] = e3*inv;
    }
    __syncthreads();

    if (t < 32) {
        int h = t >> 2, p = t & 3;
        float lx = fminf(fmaxf(sref[0] + lg[2 + h * 8 + p * 2 + 0], 0.f), 1.f);
        float ly = fminf(fmaxf(sref[1] + lg[2 + h * 8 + p * 2 + 1], 0.f), 1.f);
        float sx = lx * (float)(WGn - 1);
        float sy = ly * (float)(HGn - 1);
        float x0f = floorf(sx), y0f = floorf(sy);
        int x0 = min(max((int)x0f, 0), WGn - 1);
        int y0 = min(max((int)y0f, 0), HGn - 1);
        int x1i = min(x0 + 1, WGn - 1);
        int y1i = min(y0 + 1, HGn - 1);
        float wx1 = sx - x0f, wx0 = 1.f - wx1;
        float wy1 = sy - y0f, wy0 = 1.f - wy1;
        float wp = swts[t];
        int rowb = b * HWn;
        int base = t * 4;
        srow[base + 0] = rowb + y0  * WGn + x0;  swt[base + 0] = wp * wx0 * wy0;
        srow[base + 1] = rowb + y1i * WGn + x0;  swt[base + 1] = wp * wx0 * wy1;
        srow[base + 2] = rowb + y0  * WGn + x1i; swt[base + 2] = wp * wx1 * wy0;
        srow[base + 3] = rowb + y1i * WGn + x1i; swt[base + 3] = wp * wx1 * wy1;
    }
    __syncthreads();

#pragma unroll
    for (int h = 0; h < Hn; h++) {
        float acc = 0.f;
#pragma unroll
        for (int i = 0; i < 16; i++)
            acc += swt[h * 16 + i] * memory[(size_t)srow[h * 16 + i] * Dn + t];
        me[((size_t)h * BQ + bq) * Dn + t] = __float2half(acc);
    }
}

// ---------------- launch ----------------
extern "C" void kernel_launch(void* const* d_in, const int* in_sizes, int n_in,
                              void* d_out, int out_size)
{
    const float* tgt        = (const float*)d_in[0];
    const float* memory     = (const float*)d_in[1];
    const float* in_proj_w  = (const float*)d_in[2];
    const float* in_proj_b  = (const float*)d_in[3];
    const float* out_proj_w = (const float*)d_in[4];
    const float* out_proj_b = (const float*)d_in[5];
    const float* norm1_g    = (const float*)d_in[6];
    const float* norm1_b    = (const float*)d_in[7];
    const float* ref_w      = (const float*)d_in[8];
    const float* ref_b      = (const float*)d_in[9];
    const float* off_w      = (const float*)d_in[10];
    const float* off_b      = (const float*)d_in[11];
    const float* attw_w     = (const float*)d_in[12];
    const float* attw_b     = (const float*)d_in[13];
    const float* vproj_w    = (const float*)d_in[14];
    const float* vproj_b    = (const float*)d_in[15];
    const float* oproj_w    = (const float*)d_in[16];
    const float* oproj_b    = (const float*)d_in[17];
    const float* norm2_g    = (const float*)d_in[18];
    const float* norm2_b    = (const float*)d_in[19];
    const float* lin1_w     = (const float*)d_in[20];
    const float* lin1_b     = (const float*)d_in[21];
    const float* lin2_w     = (const float*)d_in[22];
    const float* lin2_b     = (const float*)d_in[23];
    const float* norm3_g    = (const float*)d_in[24];
    const float* norm3_b    = (const float*)d_in[25];
    float* out = (float*)d_out;

    float *qkv, *x1, *x2, *tmp, *wcat, *bcat, *lgb;
    __half *sah, *x2h, *cah, *meh, *ffh, *tgth;
    uint32_t *pip, *pop, *poq, *pvp, *p1w, *p2w;
    cudaGetSymbolAddress((void**)&qkv,  g_qkv);
    cudaGetSymbolAddress((void**)&sah,  g_sah);
    cudaGetSymbolAddress((void**)&x1,   g_x1);
    cudaGetSymbolAddress((void**)&x2,   g_x2);
    cudaGetSymbolAddress((void**)&x2h,  g_x2h);
    cudaGetSymbolAddress((void**)&tmp,  g_tmp);
    cudaGetSymbolAddress((void**)&cah,  g_cah);
    cudaGetSymbolAddress((void**)&meh,  g_meh);
    cudaGetSymbolAddress((void**)&ffh,  g_ffh);
    cudaGetSymbolAddress((void**)&wcat, g_wcat);
    cudaGetSymbolAddress((void**)&bcat, g_bcat);
    cudaGetSymbolAddress((void**)&lgb,  g_lg);
    cudaGetSymbolAddress((void**)&tgth, g_tgth);
    cudaGetSymbolAddress((void**)&pip,  g_pip);
    cudaGetSymbolAddress((void**)&pop,  g_pop);
    cudaGetSymbolAddress((void**)&poq,  g_poq);
    cudaGetSymbolAddress((void**)&pvp,  g_pvp);
    cudaGetSymbolAddress((void**)&p1w,  g_p1w);
    cudaGetSymbolAddress((void**)&p2w,  g_p2w);

    const int smemh = (3 * 64 * HAP + 3 * 16 * BPITCH) * 4;  // 41472
    cudaFuncSetAttribute((const void*)gemm_fp16_async, cudaFuncAttributeMaxDynamicSharedMemorySize, smemh);

    // 0. pack all weights + tgt to fp16 (5216 blocks); concat logits weights (fp32)
    packw_kernel<<<5216, 256>>>(in_proj_w, out_proj_w, oproj_w, vproj_w, lin1_w, lin2_w, tgt,
                                pip, pop, poq, pvp, p1w, p2w, (uint32_t*)tgth);
    concat_w_kernel<<<128, 256>>>(ref_w, ref_b, off_w, off_b, attw_w, attw_b, wcat, bcat);
    // 1. qkv projection [4800,256]@[256,768] — fp16, fp32 out
    gemm_fp16_async<<<dim3(768 / TBN, BQ / 64), 256, smemh>>>(tgth, pip, in_proj_b, qkv, BQ, 768, Dn, 0, 0);
    // 2. fused self-attention (2q/thread, cp.async pipelined tiles), half out
    flash_kernel<<<Bn * Hn, 160>>>(qkv, sah);
    // 3. out_proj — fp16, fp32 out
    gemm_fp16_async<<<dim3(Dn / TBN, BQ / 64), 256, smemh>>>(sah, pop, out_proj_b, tmp, BQ, Dn, Dn, 0, 0);
    // 4. x1 = LN(tgt + sa_out)
    add_ln_kernel<<<BQ, Dn>>>(tgt, tmp, norm1_g, norm1_b, x1, nullptr);
    // 5. logits — fp32 (accuracy-critical)
    gemm_f32_kernel<<<dim3(128 / BNf, BQ / BM), 256>>>(x1, wcat, bcat, lgb, BQ, 128, Dn);
    // 6. sampler2: gather raw memory -> half m_eff
    sampler2_kernel<<<BQ, 256>>>(lgb, memory, meh);
    // 7. per-head projection — fp16, half out
    gemm_proj_h<<<dim3(Hn, BQ / 64), 128>>>(meh, pvp, vproj_b, cah);
    // 8. oproj — fp16, fp32 out
    gemm_fp16_async<<<dim3(Dn / TBN, BQ / 64), 256, smemh>>>(cah, poq, oproj_b, tmp, BQ, Dn, Dn, 0, 0);
    // 9. x2 = LN(x1 + ca_out); x2h = half(x2)
    add_ln_kernel<<<BQ, Dn>>>(x1, tmp, norm2_g, norm2_b, x2, x2h);
    // 10. FFN lin1 + ReLU — fp16, half out
    gemm_fp16_async<<<dim3(Fn / TBN, BQ / 64), 256, smemh>>>(x2h, p1w, lin1_b, ffh, BQ, Fn, Dn, 1, 1);
    // 11. FFN lin2 — fp16, fp32 out
    gemm_fp16_async<<<dim3(Dn / TBN, BQ / 64), 256, smemh>>>(ffh, p2w, lin2_b, tmp, BQ, Dn, Fn, 0, 0);
    // 12. out = LN(x2 + ffn)
    add_ln_kernel<<<BQ, Dn>>>(x2, tmp, norm3_g, norm3_b, out, nullptr);
}